// round 12
// baseline (speedup 1.0000x reference)
#include <cuda_runtime.h>
#include <cuda_fp16.h>
#include <cstdint>

// out[8192,4096] = x[8192,4096] @ W[4096,4096]^T,  W = (q - zp)*scale
// fp16 HMMA (mma.sync.m16n8k16, fp32 accum). cp.async.bulk from pre-swizzled
// scratch; register ping-pong; BK=64, 4-stage ring; PERSISTENT CTAs (grid
// = 148): one continuous pipeline across ~7 tiles per CTA, epilogue/prologue
// of successive tiles overlap with the ring fills.
#define MDIM 8192
#define KDIM 4096
#define NDIM 4096

static constexpr int BM = 128, BN = 256, BK = 64;
static constexpr int A_BLK = BM * BK * 2;     // 16384 B per (m-tile, k-chunk)
static constexpr int B_BLK = BN * BK * 2;     // 32768 B
static constexpr int STAGE = A_BLK + B_BLK;   // 49152
static constexpr int ST = 4;
static constexpr int KT = KDIM / BK;          // 64 chunks per tile
static constexpr int SMEM_TOTAL = 1024 + ST * STAGE;  // 197632
static constexpr int NTILES = (MDIM / BM) * (NDIM / BN);  // 1024
static constexpr int NSM = 148;

// tiled+swizzled scratch: A: [64 mt][64 kt][16KB], B: [16 nt][64 kt][32KB]
// row r holds its 128B K-slice; 16B unit u at offset r*128 + (u^(r&7))*16.
__device__ uint4 g_xa[(size_t)MDIM * KDIM * 2 / 16];
__device__ uint4 g_wb[(size_t)NDIM * KDIM * 2 / 16];

__device__ __forceinline__ uint32_t smem_to_u32(const void* p) {
    uint32_t a;
    asm("{ .reg .u64 t; cvta.to.shared.u64 t, %1; cvt.u32.u64 %0, t; }"
        : "=r"(a) : "l"(p));
    return a;
}

#define MBARRIER_INIT(addr, cnt) \
    asm volatile("mbarrier.init.shared.b64 [%0], %1;" :: "r"((uint32_t)(addr)), "r"((uint32_t)(cnt)) : "memory")
#define MBARRIER_ARRIVE(addr) \
    asm volatile("mbarrier.arrive.shared.b64 _, [%0];" :: "r"((uint32_t)(addr)) : "memory")
#define MBARRIER_EXPECT_TX(addr, bytes) \
    asm volatile("mbarrier.arrive.expect_tx.shared.b64 _, [%0], %1;" :: "r"((uint32_t)(addr)), "r"((uint32_t)(bytes)) : "memory")

__device__ __forceinline__ uint32_t mbar_try_once(uint32_t mbar, uint32_t parity) {
    uint32_t done;
    asm volatile(
        "{\n\t.reg .pred p;\n\t"
        "mbarrier.try_wait.parity.acquire.cta.shared::cta.b64 p, [%1], %2;\n\t"
        "selp.b32 %0, 1, 0, p;\n\t}"
        : "=r"(done) : "r"(mbar), "r"(parity) : "memory");
    return done;
}

#define MBARRIER_WAIT_PARITY(mbar_smem_addr, phase_parity) do { \
    uint32_t _mbar = (uint32_t)(mbar_smem_addr); \
    uint32_t _parity = (uint32_t)(phase_parity); \
    uint32_t _done; \
    asm volatile( \
        "{\n\t.reg .pred p;\n\t" \
        "mbarrier.try_wait.parity.acquire.cta.shared::cta.b64 p, [%1], %2;\n\t" \
        "selp.b32 %0, 1, 0, p;\n\t}" \
        : "=r"(_done) : "r"(_mbar), "r"(_parity) : "memory"); \
    if (!_done) { \
        asm volatile( \
            "{\n\t.reg .pred P1;\n\t" \
            "WAIT_LOOP_%=:\n\t" \
            "mbarrier.try_wait.parity.acquire.cta.shared::cta.b64 P1, [%0], %1, 0x989680;\n\t" \
            "@P1 bra.uni WAIT_DONE_%=;\n\t" \
            "bra.uni WAIT_LOOP_%=;\n\t" \
            "WAIT_DONE_%=:\n\t}" \
            :: "r"(_mbar), "r"(_parity) : "memory"); \
    } \
} while(0)

#define BULK_G2S(dst, src, bytes, mbar) \
    asm volatile("cp.async.bulk.shared::cluster.global.mbarrier::complete_tx::bytes [%0], [%1], %2, [%3];" \
        :: "r"((uint32_t)(dst)), "l"(src), "r"((uint32_t)(bytes)), "r"((uint32_t)(mbar)) : "memory")

#define LDMATRIX_X4(r0, r1, r2, r3, addr) \
    asm volatile("ldmatrix.sync.aligned.m8n8.x4.shared.b16 {%0,%1,%2,%3}, [%4];" \
        : "=r"(r0), "=r"(r1), "=r"(r2), "=r"(r3) : "r"(addr))

#define MMA_16816(c, a0, a1, a2, a3, b0, b1) \
    asm volatile("mma.sync.aligned.m16n8k16.row.col.f32.f16.f16.f32 " \
        "{%0,%1,%2,%3}, {%4,%5,%6,%7}, {%8,%9}, {%0,%1,%2,%3};" \
        : "+f"((c)[0]), "+f"((c)[1]), "+f"((c)[2]), "+f"((c)[3]) \
        : "r"(a0), "r"(a1), "r"(a2), "r"(a3), "r"(b0), "r"(b1))

// ------------------------------- prep kernel -------------------------------
static constexpr int XBLKS = (int)(((size_t)MDIM * KDIM / 8) / 256);  // 16384
static constexpr int WBLKS = (int)(((size_t)NDIM * KDIM / 8) / 256);  // 8192

__global__ void __launch_bounds__(256) prep_kernel(const float* __restrict__ x,
                                                   const int* __restrict__ q,
                                                   const int* __restrict__ zp) {
    if (blockIdx.x < XBLKS) {
        size_t t = (size_t)blockIdx.x * blockDim.x + threadIdx.x;  // one 16B unit
        int m = (int)(t >> 9);
        int k = ((int)t & 511) * 8;
        const float4* src = reinterpret_cast<const float4*>(x + (size_t)m * KDIM + k);
        float4 v0 = src[0], v1 = src[1];
        __half2 h0 = __floats2half2_rn(v0.x, v0.y);
        __half2 h1 = __floats2half2_rn(v0.z, v0.w);
        __half2 h2 = __floats2half2_rn(v1.x, v1.y);
        __half2 h3 = __floats2half2_rn(v1.z, v1.w);
        uint4 o;
        o.x = *reinterpret_cast<uint32_t*>(&h0);
        o.y = *reinterpret_cast<uint32_t*>(&h1);
        o.z = *reinterpret_cast<uint32_t*>(&h2);
        o.w = *reinterpret_cast<uint32_t*>(&h3);
        int mt = m >> 7, r = m & 127, kt = k >> 6, kc8 = (k & 63) >> 3;
        uint32_t off = (uint32_t)r * 128 + (uint32_t)((kc8 ^ (r & 7)) * 16);
        g_xa[((size_t)(mt * KT + kt) * A_BLK + off) >> 4] = o;
    } else {
        int z = __ldg(zp);
        size_t t = (size_t)(blockIdx.x - XBLKS) * blockDim.x + threadIdx.x;
        int n = (int)(t >> 9);
        int k = ((int)t & 511) * 8;
        const int4* src = reinterpret_cast<const int4*>(q + (size_t)n * KDIM + k);
        int4 q0 = src[0], q1 = src[1];
        __half2 h0 = __floats2half2_rn((float)(q0.x - z), (float)(q0.y - z));
        __half2 h1 = __floats2half2_rn((float)(q0.z - z), (float)(q0.w - z));
        __half2 h2 = __floats2half2_rn((float)(q1.x - z), (float)(q1.y - z));
        __half2 h3 = __floats2half2_rn((float)(q1.z - z), (float)(q1.w - z));
        uint4 o;
        o.x = *reinterpret_cast<uint32_t*>(&h0);
        o.y = *reinterpret_cast<uint32_t*>(&h1);
        o.z = *reinterpret_cast<uint32_t*>(&h2);
        o.w = *reinterpret_cast<uint32_t*>(&h3);
        int nt = n >> 8, r = n & 255, kt = k >> 6, kc8 = (k & 63) >> 3;
        uint32_t off = (uint32_t)r * 128 + (uint32_t)((kc8 ^ (r & 7)) * 16);
        g_wb[((size_t)(nt * KT + kt) * B_BLK + off) >> 4] = o;
    }
}

// ------------------------------- GEMM --------------------------------------
// Persistent: grid = 148; CTA handles tiles bid, bid+148, ... < 1024 with one
// continuous 4-stage ring. 8 warps: 2(M) x 4(N), warp tile 64x64.
__global__ void __launch_bounds__(256, 1)
gemm_kernel(const float* __restrict__ bias,
            const float* __restrict__ wscale,
            float* __restrict__ out) {
    extern __shared__ char smem[];
    const uint32_t sbase = smem_to_u32(smem);
    const int tid = threadIdx.x;
    const int lane = tid & 31;
    const int wid = tid >> 5;
    const int warp_m = wid & 1;
    const int warp_n = wid >> 1;
    const int bid = blockIdx.x;

    const int my_nt = (NTILES - 1 - bid) / NSM + 1;     // 6 or 7 tiles
    const int total_c = my_nt * KT;

    // tile id -> (m0, n0) via the L2 swizzle (8 mt-group x 16 nt sweep)
    auto tile_mn = [&](int t, int& m0, int& n0) {
        int grp = t >> 7, rr = t & 127;
        m0 = (grp * 8 + (rr & 7)) * BM;
        n0 = (rr >> 3) * BN;
    };
    // global chunk j -> gmem srcs
    auto chunk_src = [&](int j, const char*& sA, const char*& sB) {
        int t = bid + NSM * (j >> 6);
        int kc = j & 63;
        int grp = t >> 7, rr = t & 127;
        int mt = grp * 8 + (rr & 7), nt = rr >> 3;
        sA = (const char*)g_xa + ((size_t)mt * KT + kc) * A_BLK;
        sB = (const char*)g_wb + ((size_t)nt * KT + kc) * B_BLK;
    };

    const uint32_t fullb = sbase, emptyb = sbase + 128;
    if (tid == 0) {
        #pragma unroll
        for (int s = 0; s < ST; s++) {
            MBARRIER_INIT(fullb + 16 * s, 1);
            MBARRIER_INIT(emptyb + 16 * s, 8);
        }
    }
    __syncthreads();

    if (tid == 0) {
        #pragma unroll
        for (int j = 0; j < 3; j++) {
            const char *sA, *sB;
            chunk_src(j, sA, sB);
            MBARRIER_EXPECT_TX(fullb + 16 * j, STAGE);
            BULK_G2S(sbase + 1024 + j * STAGE, sA, A_BLK, fullb + 16 * j);
            BULK_G2S(sbase + 1024 + j * STAGE + A_BLK, sB, B_BLK, fullb + 16 * j);
        }
    }

    // per-lane ldmatrix components. Row pitch = 128B; lane row-in-16 = rin.
    const int rin = ((lane >> 3) & 1) * 8 + (lane & 7);
    const int kh = lane >> 4;
    const int xr = rin & 7;
    uint32_t off_k[4];
    #pragma unroll
    for (int ks = 0; ks < 4; ks++)
        off_k[ks] = (uint32_t)(((ks * 2 + kh) ^ xr) * 16);
    const uint32_t aBase = (uint32_t)((warp_m * 64 + rin) * 128);
    const uint32_t bBase = (uint32_t)(A_BLK + (warp_n * 64 + rin) * 128);

    uint32_t a[2][4][4], b[2][4][4];
    float acc[4][8][4];
    #pragma unroll
    for (int i = 0; i < 4; i++)
        #pragma unroll
        for (int j = 0; j < 8; j++)
            #pragma unroll
            for (int c = 0; c < 4; c++) acc[i][j][c] = 0.f;

    auto ldsm_one = [&](int d, int li, uint32_t sa, uint32_t ko) {
        if (li < 4) {
            LDMATRIX_X4(a[d][li][0], a[d][li][1], a[d][li][2], a[d][li][3],
                        sa + aBase + li * 2048 + ko);
        } else {
            int nj = li - 4;
            LDMATRIX_X4(b[d][nj][0], b[d][nj][1], b[d][nj][2], b[d][nj][3],
                        sa + bBase + nj * 2048 + ko);
        }
    };
    auto mma_one = [&](int d, int u) {
        int mi = u >> 3, v = u & 7;
        int nj = v >> 1, tb = v & 1;
        MMA_16816(acc[mi][v],
                  a[d][mi][0], a[d][mi][1], a[d][mi][2], a[d][mi][3],
                  b[d][nj][tb], b[d][nj][tb + 2]);
    };
    auto step_interleaved = [&](int d, uint32_t sa_n, uint32_t ko_n) {
        #pragma unroll
        for (int u = 0; u < 32; u++) {
            if ((u & 3) == 0) ldsm_one(d ^ 1, u >> 2, sa_n, ko_n);
            mma_one(d, u);
        }
    };
    const float scale = __ldg(wscale);
    auto epilogue = [&](int m0, int n0) {
        const int g = lane >> 2, tg = lane & 3;
        #pragma unroll
        for (int mi = 0; mi < 4; mi++) {
            #pragma unroll
            for (int v = 0; v < 8; v++) {
                int col = n0 + warp_n * 64 + v * 8 + tg * 2;
                float2 bb = *reinterpret_cast<const float2*>(bias + col);
                #pragma unroll
                for (int rh = 0; rh < 2; rh++) {
                    int row = m0 + warp_m * 64 + mi * 16 + g + rh * 8;
                    float2 o;
                    o.x = acc[mi][v][rh * 2 + 0] * scale + bb.x;
                    o.y = acc[mi][v][rh * 2 + 1] * scale + bb.y;
                    *reinterpret_cast<float2*>(out + (size_t)row * NDIM + col) = o;
                    acc[mi][v][rh * 2 + 0] = 0.f;
                    acc[mi][v][rh * 2 + 1] = 0.f;
                }
            }
        }
    };

    // prologue: wait chunk 0, load its ks0 frags into buf 0
    MBARRIER_WAIT_PARITY(fullb, 0);
    {
        #pragma unroll
        for (int li = 0; li < 8; li++) ldsm_one(0, li, sbase + 1024, off_k[0]);
    }

    int cur = 0;
    #pragma unroll 1
    for (int c = 0; c < total_c; c++) {
        const int s = c & 3;
        const uint32_t sa = sbase + 1024 + s * STAGE;
        const int s2 = (c + 1) & 3;
        const uint32_t ph2 = (uint32_t)(((c + 1) >> 2) & 1);

        // ks=0: MMA on cur with ks1-prefetch interleaved
        step_interleaved(cur, sa, off_k[1]);
        cur ^= 1;

        // producer: RR warp (c&7), lane 0 fills global chunk c+3
        if (wid == (c & 7) && lane == 0) {
            int j = c + 3;
            if (j < total_c) {
                int sj = j & 3;
                if (j >= 4) MBARRIER_WAIT_PARITY(emptyb + 16 * sj, ((j - 4) >> 2) & 1);
                const char *sA, *sB;
                chunk_src(j, sA, sB);
                MBARRIER_EXPECT_TX(fullb + 16 * sj, STAGE);
                BULK_G2S(sbase + 1024 + sj * STAGE, sA, A_BLK, fullb + 16 * sj);
                BULK_G2S(sbase + 1024 + sj * STAGE + A_BLK, sB, B_BLK, fullb + 16 * sj);
            }
        }

        // ks=1: MMA with ks2-prefetch interleaved
        step_interleaved(cur, sa, off_k[2]);
        cur ^= 1;

        // ks=2: peek next chunk's full, MMA with ks3-prefetch, release stage
        uint32_t nextReady = 0;
        if (c + 1 < total_c) nextReady = mbar_try_once(fullb + 16 * s2, ph2);
        step_interleaved(cur, sa, off_k[3]);
        if (lane == 0) MBARRIER_ARRIVE(emptyb + 16 * s);
        cur ^= 1;

        // ks=3: 16 MMAs; wait (miss only); last 16 MMAs with next ks0 prefetch
        {
            #pragma unroll
            for (int u = 0; u < 16; u++) mma_one(cur, u);
            if (c + 1 < total_c) {
                if (!nextReady) MBARRIER_WAIT_PARITY(fullb + 16 * s2, ph2);
                const uint32_t sa2 = sbase + 1024 + s2 * STAGE;
                #pragma unroll
                for (int u = 16; u < 32; u++) {
                    if ((u & 1) == 0) ldsm_one(cur ^ 1, (u - 16) >> 1, sa2, off_k[0]);
                    mma_one(cur, u);
                }
            } else {
                #pragma unroll
                for (int u = 16; u < 32; u++) mma_one(cur, u);
            }
            cur ^= 1;
        }

        // tile boundary: store + reset acc (next tile's fills already queued)
        if ((c & 63) == 63) {
            int m0, n0;
            tile_mn(bid + NSM * (c >> 6), m0, n0);
            epilogue(m0, n0);
        }
    }
}

// ------------------------------- launch ------------------------------------
extern "C" void kernel_launch(void* const* d_in, const int* in_sizes, int n_in,
                              void* d_out, int out_size) {
    const float* x     = (const float*)d_in[0];
    const int*   q     = (const int*)d_in[1];
    const int*   zp    = (const int*)d_in[2];
    const float* scale = (const float*)d_in[3];
    const float* bias  = (const float*)d_in[4];
    float* out = (float*)d_out;

    cudaFuncSetAttribute(gemm_kernel, cudaFuncAttributeMaxDynamicSharedMemorySize, SMEM_TOTAL);

    prep_kernel<<<XBLKS + WBLKS, 256>>>(x, q, zp);
    gemm_kernel<<<NSM, 256, SMEM_TOTAL>>>(bias, scale, out);
}

// round 13
// speedup vs baseline: 1.1697x; 1.1697x over previous
#include <cuda_runtime.h>
#include <cuda_fp16.h>
#include <cstdint>

// out[8192,4096] = x[8192,4096] @ W[4096,4096]^T,  W = (q - zp)*scale
// fp16 HMMA (mma.sync.m16n8k16, fp32 accum). cp.async.bulk from pre-swizzled
// scratch; register ping-pong; BK=64, 4-stage ring. CLEAN persistent CTAs:
// R11's inner loop unchanged, outer tile loop; ring parity runs on a global
// chunk counter so the pipeline never drains across tile boundaries.
#define MDIM 8192
#define KDIM 4096
#define NDIM 4096

static constexpr int BM = 128, BN = 256, BK = 64;
static constexpr int A_BLK = BM * BK * 2;     // 16384 B
static constexpr int B_BLK = BN * BK * 2;     // 32768 B
static constexpr int STAGE = A_BLK + B_BLK;   // 49152
static constexpr int ST = 4;
static constexpr int KT = KDIM / BK;          // 64 chunks per tile
static constexpr int SMEM_TOTAL = 1024 + ST * STAGE;  // 197632
static constexpr int NTILES = (MDIM / BM) * (NDIM / BN);  // 1024
static constexpr int NSM = 148;

__device__ uint4 g_xa[(size_t)MDIM * KDIM * 2 / 16];
__device__ uint4 g_wb[(size_t)NDIM * KDIM * 2 / 16];

__device__ __forceinline__ uint32_t smem_to_u32(const void* p) {
    uint32_t a;
    asm("{ .reg .u64 t; cvta.to.shared.u64 t, %1; cvt.u32.u64 %0, t; }"
        : "=r"(a) : "l"(p));
    return a;
}

#define MBARRIER_INIT(addr, cnt) \
    asm volatile("mbarrier.init.shared.b64 [%0], %1;" :: "r"((uint32_t)(addr)), "r"((uint32_t)(cnt)) : "memory")
#define MBARRIER_ARRIVE(addr) \
    asm volatile("mbarrier.arrive.shared.b64 _, [%0];" :: "r"((uint32_t)(addr)) : "memory")
#define MBARRIER_EXPECT_TX(addr, bytes) \
    asm volatile("mbarrier.arrive.expect_tx.shared.b64 _, [%0], %1;" :: "r"((uint32_t)(addr)), "r"((uint32_t)(bytes)) : "memory")

__device__ __forceinline__ uint32_t mbar_try_once(uint32_t mbar, uint32_t parity) {
    uint32_t done;
    asm volatile(
        "{\n\t.reg .pred p;\n\t"
        "mbarrier.try_wait.parity.acquire.cta.shared::cta.b64 p, [%1], %2;\n\t"
        "selp.b32 %0, 1, 0, p;\n\t}"
        : "=r"(done) : "r"(mbar), "r"(parity) : "memory");
    return done;
}

#define MBARRIER_WAIT_PARITY(mbar_smem_addr, phase_parity) do { \
    uint32_t _mbar = (uint32_t)(mbar_smem_addr); \
    uint32_t _parity = (uint32_t)(phase_parity); \
    uint32_t _done; \
    asm volatile( \
        "{\n\t.reg .pred p;\n\t" \
        "mbarrier.try_wait.parity.acquire.cta.shared::cta.b64 p, [%1], %2;\n\t" \
        "selp.b32 %0, 1, 0, p;\n\t}" \
        : "=r"(_done) : "r"(_mbar), "r"(_parity) : "memory"); \
    if (!_done) { \
        asm volatile( \
            "{\n\t.reg .pred P1;\n\t" \
            "WAIT_LOOP_%=:\n\t" \
            "mbarrier.try_wait.parity.acquire.cta.shared::cta.b64 P1, [%0], %1, 0x989680;\n\t" \
            "@P1 bra.uni WAIT_DONE_%=;\n\t" \
            "bra.uni WAIT_LOOP_%=;\n\t" \
            "WAIT_DONE_%=:\n\t}" \
            :: "r"(_mbar), "r"(_parity) : "memory"); \
    } \
} while(0)

#define BULK_G2S(dst, src, bytes, mbar) \
    asm volatile("cp.async.bulk.shared::cluster.global.mbarrier::complete_tx::bytes [%0], [%1], %2, [%3];" \
        :: "r"((uint32_t)(dst)), "l"(src), "r"((uint32_t)(bytes)), "r"((uint32_t)(mbar)) : "memory")

#define LDMATRIX_X4(r0, r1, r2, r3, addr) \
    asm volatile("ldmatrix.sync.aligned.m8n8.x4.shared.b16 {%0,%1,%2,%3}, [%4];" \
        : "=r"(r0), "=r"(r1), "=r"(r2), "=r"(r3) : "r"(addr))

#define MMA_16816(c, a0, a1, a2, a3, b0, b1) \
    asm volatile("mma.sync.aligned.m16n8k16.row.col.f32.f16.f16.f32 " \
        "{%0,%1,%2,%3}, {%4,%5,%6,%7}, {%8,%9}, {%0,%1,%2,%3};" \
        : "+f"((c)[0]), "+f"((c)[1]), "+f"((c)[2]), "+f"((c)[3]) \
        : "r"(a0), "r"(a1), "r"(a2), "r"(a3), "r"(b0), "r"(b1))

// ------------------------------- prep kernel -------------------------------
static constexpr int XBLKS = (int)(((size_t)MDIM * KDIM / 8) / 256);  // 16384
static constexpr int WBLKS = (int)(((size_t)NDIM * KDIM / 8) / 256);  // 8192

__global__ void __launch_bounds__(256) prep_kernel(const float* __restrict__ x,
                                                   const int* __restrict__ q,
                                                   const int* __restrict__ zp) {
    if (blockIdx.x < XBLKS) {
        size_t t = (size_t)blockIdx.x * blockDim.x + threadIdx.x;  // one 16B unit
        int m = (int)(t >> 9);
        int k = ((int)t & 511) * 8;
        const float4* src = reinterpret_cast<const float4*>(x + (size_t)m * KDIM + k);
        float4 v0 = src[0], v1 = src[1];
        __half2 h0 = __floats2half2_rn(v0.x, v0.y);
        __half2 h1 = __floats2half2_rn(v0.z, v0.w);
        __half2 h2 = __floats2half2_rn(v1.x, v1.y);
        __half2 h3 = __floats2half2_rn(v1.z, v1.w);
        uint4 o;
        o.x = *reinterpret_cast<uint32_t*>(&h0);
        o.y = *reinterpret_cast<uint32_t*>(&h1);
        o.z = *reinterpret_cast<uint32_t*>(&h2);
        o.w = *reinterpret_cast<uint32_t*>(&h3);
        int mt = m >> 7, r = m & 127, kt = k >> 6, kc8 = (k & 63) >> 3;
        uint32_t off = (uint32_t)r * 128 + (uint32_t)((kc8 ^ (r & 7)) * 16);
        g_xa[((size_t)(mt * KT + kt) * A_BLK + off) >> 4] = o;
    } else {
        int z = __ldg(zp);
        size_t t = (size_t)(blockIdx.x - XBLKS) * blockDim.x + threadIdx.x;
        int n = (int)(t >> 9);
        int k = ((int)t & 511) * 8;
        const int4* src = reinterpret_cast<const int4*>(q + (size_t)n * KDIM + k);
        int4 q0 = src[0], q1 = src[1];
        __half2 h0 = __floats2half2_rn((float)(q0.x - z), (float)(q0.y - z));
        __half2 h1 = __floats2half2_rn((float)(q0.z - z), (float)(q0.w - z));
        __half2 h2 = __floats2half2_rn((float)(q1.x - z), (float)(q1.y - z));
        __half2 h3 = __floats2half2_rn((float)(q1.z - z), (float)(q1.w - z));
        uint4 o;
        o.x = *reinterpret_cast<uint32_t*>(&h0);
        o.y = *reinterpret_cast<uint32_t*>(&h1);
        o.z = *reinterpret_cast<uint32_t*>(&h2);
        o.w = *reinterpret_cast<uint32_t*>(&h3);
        int nt = n >> 8, r = n & 255, kt = k >> 6, kc8 = (k & 63) >> 3;
        uint32_t off = (uint32_t)r * 128 + (uint32_t)((kc8 ^ (r & 7)) * 16);
        g_wb[((size_t)(nt * KT + kt) * B_BLK + off) >> 4] = o;
    }
}

// ------------------------------- GEMM --------------------------------------
// Persistent grid=148. Per tile: R11 inner loop; ring continues across tiles.
__global__ void __launch_bounds__(256, 1)
gemm_kernel(const float* __restrict__ bias,
            const float* __restrict__ wscale,
            float* __restrict__ out) {
    extern __shared__ char smem[];
    const uint32_t sbase = smem_to_u32(smem);
    const int tid = threadIdx.x;
    const int lane = tid & 31;
    const int wid = tid >> 5;
    const int warp_m = wid & 1;
    const int warp_n = wid >> 1;
    const int bid = blockIdx.x;

    const int my_nt = (NTILES - 1 - bid) / NSM + 1;   // 7 or 6 tiles

    // tile id -> swizzled (mt, nt)
    auto tile_mn = [&](int t, int& mt, int& nt) {
        int grp = t >> 7, rr = t & 127;
        mt = grp * 8 + (rr & 7);
        nt = rr >> 3;
    };

    const uint32_t fullb = sbase, emptyb = sbase + 128;
    if (tid == 0) {
        #pragma unroll
        for (int s = 0; s < ST; s++) {
            MBARRIER_INIT(fullb + 16 * s, 1);
            MBARRIER_INIT(emptyb + 16 * s, 8);
        }
    }
    __syncthreads();

    // current tile (ti=0) and next tile src bases
    int mt0, nt0;
    tile_mn(bid, mt0, nt0);
    const char* srcA = (const char*)g_xa + (size_t)mt0 * KT * A_BLK;
    const char* srcB = (const char*)g_wb + (size_t)nt0 * KT * B_BLK;

    if (tid == 0) {
        #pragma unroll
        for (int j = 0; j < 3; j++) {
            MBARRIER_EXPECT_TX(fullb + 16 * j, STAGE);
            BULK_G2S(sbase + 1024 + j * STAGE, srcA + (size_t)j * A_BLK, A_BLK, fullb + 16 * j);
            BULK_G2S(sbase + 1024 + j * STAGE + A_BLK, srcB + (size_t)j * B_BLK, B_BLK, fullb + 16 * j);
        }
    }

    const int rin = ((lane >> 3) & 1) * 8 + (lane & 7);
    const int kh = lane >> 4;
    const int xr = rin & 7;
    uint32_t off_k[4];
    #pragma unroll
    for (int ks = 0; ks < 4; ks++)
        off_k[ks] = (uint32_t)(((ks * 2 + kh) ^ xr) * 16);
    const uint32_t aBase = (uint32_t)((warp_m * 64 + rin) * 128);
    const uint32_t bBase = (uint32_t)(A_BLK + (warp_n * 64 + rin) * 128);

    uint32_t a[2][4][4], b[2][4][4];
    float acc[4][8][4];
    #pragma unroll
    for (int i = 0; i < 4; i++)
        #pragma unroll
        for (int j = 0; j < 8; j++)
            #pragma unroll
            for (int c = 0; c < 4; c++) acc[i][j][c] = 0.f;

    auto ldsm_one = [&](int d, int li, uint32_t sa, uint32_t ko) {
        if (li < 4) {
            LDMATRIX_X4(a[d][li][0], a[d][li][1], a[d][li][2], a[d][li][3],
                        sa + aBase + li * 2048 + ko);
        } else {
            int nj = li - 4;
            LDMATRIX_X4(b[d][nj][0], b[d][nj][1], b[d][nj][2], b[d][nj][3],
                        sa + bBase + nj * 2048 + ko);
        }
    };
    auto mma_one = [&](int d, int u) {
        int mi = u >> 3, v = u & 7;
        int nj = v >> 1, tb = v & 1;
        MMA_16816(acc[mi][v],
                  a[d][mi][0], a[d][mi][1], a[d][mi][2], a[d][mi][3],
                  b[d][nj][tb], b[d][nj][tb + 2]);
    };
    auto step_interleaved = [&](int d, uint32_t sa_n, uint32_t ko_n) {
        #pragma unroll
        for (int u = 0; u < 32; u++) {
            if ((u & 3) == 0) ldsm_one(d ^ 1, u >> 2, sa_n, ko_n);
            mma_one(d, u);
        }
    };

    // prologue: wait chunk 0, load its ks0 frags into buf 0
    MBARRIER_WAIT_PARITY(fullb, 0);
    {
        #pragma unroll
        for (int li = 0; li < 8; li++) ldsm_one(0, li, sbase + 1024, off_k[0]);
    }

    const float scale = __ldg(wscale);
    int cur = 0;

    #pragma unroll 1
    for (int ti = 0; ti < my_nt; ti++) {
        const int cbase = ti * KT;                    // global chunk base
        const bool have_next = (ti + 1 < my_nt);
        // next tile src bases (hoisted out of the inner loop)
        const char* srcA_nx = srcA;
        const char* srcB_nx = srcB;
        if (have_next) {
            int mtn, ntn;
            tile_mn(bid + NSM * (ti + 1), mtn, ntn);
            srcA_nx = (const char*)g_xa + (size_t)mtn * KT * A_BLK;
            srcB_nx = (const char*)g_wb + (size_t)ntn * KT * B_BLK;
        }
        const bool last_tile = !have_next;

        #pragma unroll 1
        for (int kt = 0; kt < KT; kt++) {
            const int c = cbase + kt;
            const int s = c & 3;
            const uint32_t sa = sbase + 1024 + s * STAGE;
            const int s2 = (c + 1) & 3;
            const uint32_t ph2 = (uint32_t)(((c + 1) >> 2) & 1);
            const bool have_c1 = !(last_tile && kt == KT - 1);

            // ks=0: MMA on cur with ks1-prefetch interleaved
            step_interleaved(cur, sa, off_k[1]);
            cur ^= 1;

            // producer: RR warp (c&7), lane 0 fills global chunk c+3
            if (wid == (c & 7) && lane == 0) {
                int jk = kt + 3;
                bool ok = (jk < KT) || have_next;
                if (ok) {
                    int j = c + 3;
                    int sj = j & 3;
                    if (j >= 4) MBARRIER_WAIT_PARITY(emptyb + 16 * sj, ((j - 4) >> 2) & 1);
                    const char* sA;
                    const char* sB;
                    if (jk < KT) {
                        sA = srcA + (size_t)jk * A_BLK;
                        sB = srcB + (size_t)jk * B_BLK;
                    } else {
                        sA = srcA_nx + (size_t)(jk - KT) * A_BLK;
                        sB = srcB_nx + (size_t)(jk - KT) * B_BLK;
                    }
                    MBARRIER_EXPECT_TX(fullb + 16 * sj, STAGE);
                    BULK_G2S(sbase + 1024 + sj * STAGE, sA, A_BLK, fullb + 16 * sj);
                    BULK_G2S(sbase + 1024 + sj * STAGE + A_BLK, sB, B_BLK, fullb + 16 * sj);
                }
            }

            // ks=1: MMA with ks2-prefetch interleaved
            step_interleaved(cur, sa, off_k[2]);
            cur ^= 1;

            // ks=2: peek next chunk full, MMA with ks3-prefetch, release stage
            uint32_t nextReady = 0;
            if (have_c1) nextReady = mbar_try_once(fullb + 16 * s2, ph2);
            step_interleaved(cur, sa, off_k[3]);
            if (lane == 0) MBARRIER_ARRIVE(emptyb + 16 * s);
            cur ^= 1;

            // ks=3: 16 MMAs; wait on miss; last 16 MMAs + next-chunk ks0 prefetch
            {
                #pragma unroll
                for (int u = 0; u < 16; u++) mma_one(cur, u);
                if (have_c1) {
                    if (!nextReady) MBARRIER_WAIT_PARITY(fullb + 16 * s2, ph2);
                    const uint32_t sa2 = sbase + 1024 + s2 * STAGE;
                    #pragma unroll
                    for (int u = 16; u < 32; u++) {
                        if ((u & 1) == 0) ldsm_one(cur ^ 1, (u - 16) >> 1, sa2, off_k[0]);
                        mma_one(cur, u);
                    }
                } else {
                    #pragma unroll
                    for (int u = 16; u < 32; u++) mma_one(cur, u);
                }
                cur ^= 1;
            }
        }

        // epilogue for this tile (next tile's fills already in flight)
        {
            const int m0 = mt0 * BM, n0 = nt0 * BN;
            const int g = lane >> 2, tg = lane & 3;
            #pragma unroll
            for (int mi = 0; mi < 4; mi++) {
                #pragma unroll
                for (int v = 0; v < 8; v++) {
                    int col = n0 + warp_n * 64 + v * 8 + tg * 2;
                    float2 bb = *reinterpret_cast<const float2*>(bias + col);
                    #pragma unroll
                    for (int rh = 0; rh < 2; rh++) {
                        int row = m0 + warp_m * 64 + mi * 16 + g + rh * 8;
                        float2 o;
                        o.x = acc[mi][v][rh * 2 + 0] * scale + bb.x;
                        o.y = acc[mi][v][rh * 2 + 1] * scale + bb.y;
                        *reinterpret_cast<float2*>(out + (size_t)row * NDIM + col) = o;
                        acc[mi][v][rh * 2 + 0] = 0.f;
                        acc[mi][v][rh * 2 + 1] = 0.f;
                    }
                }
            }
        }

        // rotate tile state
        if (have_next) {
            tile_mn(bid + NSM * (ti + 1), mt0, nt0);
            srcA = srcA_nx;
            srcB = srcB_nx;
        }
    }
}

// ------------------------------- launch ------------------------------------
extern "C" void kernel_launch(void* const* d_in, const int* in_sizes, int n_in,
                              void* d_out, int out_size) {
    const float* x     = (const float*)d_in[0];
    const int*   q     = (const int*)d_in[1];
    const int*   zp    = (const int*)d_in[2];
    const float* scale = (const float*)d_in[3];
    const float* bias  = (const float*)d_in[4];
    float* out = (float*)d_out;

    cudaFuncSetAttribute(gemm_kernel, cudaFuncAttributeMaxDynamicSharedMemorySize, SMEM_TOTAL);

    prep_kernel<<<XBLKS + WBLKS, 256>>>(x, q, zp);
    gemm_kernel<<<NSM, 256, SMEM_TOTAL>>>(bias, scale, out);
}